// round 3
// baseline (speedup 1.0000x reference)
#include <cuda_runtime.h>

// Problem constants
#define NB   4
#define NC   128
#define C8   16
#define HH   64
#define WW   64
#define HWSZ 4096   // 64*64

// ---------------- scratch (static device globals; no runtime alloc) -------
__device__ float g_Qt [NB * C8 * HWSZ];     // [b][c8][p]
__device__ float g_Kt [NB * C8 * HWSZ];     // [b][c8][p]
__device__ float g_V  [NB * NC * HWSZ];     // [b][c][p]
__device__ float g_sel[NB * NC * HWSZ];     // [b][c][p]
__device__ float g_maxv[NB * HWSZ];
__device__ int   g_idx [NB * HWSZ];
__device__ float g_Wt [2 * NC * 9 * NC];    // [icg 256][tap 9][oc 128]
__device__ float g_WvT[NC * NC];            // [c][o]
__device__ float g_WqT[NC * C8];            // [c][o]
__device__ float g_WkT[NC * C8];            // [c][o]

// ---------------- f32x2 helpers (sm_103a packed fp32 FMA) -----------------
__device__ __forceinline__ unsigned long long pack2(float lo, float hi) {
    unsigned long long r;
    asm("mov.b64 %0, {%1, %2};" : "=l"(r)
        : "r"(__float_as_uint(lo)), "r"(__float_as_uint(hi)));
    return r;
}
__device__ __forceinline__ void unpack2(unsigned long long v, float& lo, float& hi) {
    unsigned ulo, uhi;
    asm("mov.b64 {%0, %1}, %2;" : "=r"(ulo), "=r"(uhi) : "l"(v));
    lo = __uint_as_float(ulo); hi = __uint_as_float(uhi);
}
__device__ __forceinline__ void ffma2(unsigned long long& d,
                                      unsigned long long a, unsigned long long b) {
    asm("fma.rn.f32x2 %0, %1, %2, %0;" : "+l"(d) : "l"(a), "l"(b));
}

// ---------------- K0: weight transposes -----------------------------------
__global__ void k0_transpose(const float* __restrict__ Wq,
                             const float* __restrict__ Wk,
                             const float* __restrict__ Wv,
                             const float* __restrict__ Wf) {
    int t = blockIdx.x * blockDim.x + threadIdx.x;
    int stride = gridDim.x * blockDim.x;
    // Wf [o=128][ic=256][3][3] -> Wt [ic][tap][o]
    for (int i = t; i < 256 * 9 * 128; i += stride) {
        int o = i & 127; int tap = (i >> 7) % 9; int ic = i / (128 * 9);
        g_Wt[i] = Wf[(o * 256 + ic) * 9 + tap];
    }
    // Wv [o=128][c=128] -> WvT [c][o]
    for (int i = t; i < 128 * 128; i += stride) {
        int o = i & 127; int c = i >> 7;
        g_WvT[i] = Wv[o * 128 + c];
    }
    // Wq/Wk [o=16][c=128] -> [c][o]
    for (int i = t; i < 128 * 16; i += stride) {
        int o = i & 15; int c = i >> 4;
        g_WqT[i] = Wq[o * 128 + c];
        g_WkT[i] = Wk[o * 128 + c];
    }
}

// ---------------- K1: q/k/v 1x1 projections --------------------------------
// 128 blocks (b, 128-pixel tile), 128 threads. smem-tiled GEMV batches.
__global__ __launch_bounds__(128)
void k1_qkv(const float* __restrict__ x,
            const float* __restrict__ xf,
            const float* __restrict__ xb,
            const float* __restrict__ bq,
            const float* __restrict__ bk,
            const float* __restrict__ bv) {
    __shared__ float xs[64 * 128];
    __shared__ float wsf[64 * 32];
    int b  = blockIdx.x >> 5;
    int p0 = (blockIdx.x & 31) * 128;
    int t  = threadIdx.x;

    // ---- keys (Wk @ x + bk) ----
    {
        float a[16];
#pragma unroll
        for (int o = 0; o < 16; o++) a[o] = bk[o];
        for (int cc = 0; cc < 2; cc++) {
            __syncthreads();
            for (int c = 0; c < 64; c++)
                xs[c * 128 + t] = x[(b * 128 + cc * 64 + c) * HWSZ + p0 + t];
            for (int i = t; i < 64 * 16; i += 128)
                wsf[i] = g_WkT[cc * 64 * 16 + i];
            __syncthreads();
            for (int c = 0; c < 64; c++) {
                float xv = xs[c * 128 + t];
                const float4* w4 = (const float4*)&wsf[c * 16];
#pragma unroll
                for (int o4 = 0; o4 < 4; o4++) {
                    float4 w = w4[o4];
                    a[o4 * 4 + 0] += w.x * xv; a[o4 * 4 + 1] += w.y * xv;
                    a[o4 * 4 + 2] += w.z * xv; a[o4 * 4 + 3] += w.w * xv;
                }
            }
        }
#pragma unroll
        for (int o = 0; o < 16; o++)
            g_Kt[b * (C8 * HWSZ) + o * HWSZ + p0 + t] = a[o];
    }

    // ---- queries (Wq @ x_forward + bq) ----
    {
        float a[16];
#pragma unroll
        for (int o = 0; o < 16; o++) a[o] = bq[o];
        for (int cc = 0; cc < 2; cc++) {
            __syncthreads();
            for (int c = 0; c < 64; c++)
                xs[c * 128 + t] = xf[(b * 128 + cc * 64 + c) * HWSZ + p0 + t];
            for (int i = t; i < 64 * 16; i += 128)
                wsf[i] = g_WqT[cc * 64 * 16 + i];
            __syncthreads();
            for (int c = 0; c < 64; c++) {
                float xv = xs[c * 128 + t];
                const float4* w4 = (const float4*)&wsf[c * 16];
#pragma unroll
                for (int o4 = 0; o4 < 4; o4++) {
                    float4 w = w4[o4];
                    a[o4 * 4 + 0] += w.x * xv; a[o4 * 4 + 1] += w.y * xv;
                    a[o4 * 4 + 2] += w.z * xv; a[o4 * 4 + 3] += w.w * xv;
                }
            }
        }
#pragma unroll
        for (int o = 0; o < 16; o++)
            g_Qt[b * (C8 * HWSZ) + o * HWSZ + p0 + t] = a[o];
    }

    // ---- values (Wv @ x_backward + bv), 4 output groups of 32 ----
    for (int og = 0; og < 4; og++) {
        float a[32];
#pragma unroll
        for (int o = 0; o < 32; o++) a[o] = bv[og * 32 + o];
        for (int cc = 0; cc < 2; cc++) {
            __syncthreads();
            for (int c = 0; c < 64; c++)
                xs[c * 128 + t] = xb[(b * 128 + cc * 64 + c) * HWSZ + p0 + t];
            for (int i = t; i < 64 * 32; i += 128) {
                int c = i >> 5, o = i & 31;
                wsf[i] = g_WvT[(cc * 64 + c) * 128 + og * 32 + o];
            }
            __syncthreads();
            for (int c = 0; c < 64; c++) {
                float xv = xs[c * 128 + t];
                const float4* w4 = (const float4*)&wsf[c * 32];
#pragma unroll
                for (int o4 = 0; o4 < 8; o4++) {
                    float4 w = w4[o4];
                    a[o4 * 4 + 0] += w.x * xv; a[o4 * 4 + 1] += w.y * xv;
                    a[o4 * 4 + 2] += w.z * xv; a[o4 * 4 + 3] += w.w * xv;
                }
            }
        }
#pragma unroll
        for (int o = 0; o < 32; o++)
            g_V[(b * 128 + og * 32 + o) * HWSZ + p0 + t] = a[o];
    }
}

// ---------------- K2: attention row max/argmax -----------------------------
// 512 blocks x 256 threads. Block = 32 key rows of one batch; warp owns 4.
__global__ __launch_bounds__(256)
void k2_attn() {
    __shared__ float Qs[16 * 512];
    __shared__ float Ks[16 * 32];
    int b     = blockIdx.x >> 7;
    int kbase = (blockIdx.x & 127) * 32;
    int t = threadIdx.x, lane = t & 31, w = t >> 5;

    for (int i = t; i < 512; i += 256) {
        int c = i >> 5, kk = i & 31;
        Ks[c * 32 + kk] = g_Kt[b * (C8 * HWSZ) + c * HWSZ + kbase + kk];
    }
    __syncthreads();

    float key[64];
#pragma unroll
    for (int r = 0; r < 4; r++)
#pragma unroll
        for (int c = 0; c < 16; c++)
            key[r * 16 + c] = Ks[c * 32 + w * 4 + r];

    float m[4]; int id[4];
#pragma unroll
    for (int r = 0; r < 4; r++) { m[r] = -3.4e38f; id[r] = 0; }

    for (int ch = 0; ch < 8; ch++) {
        __syncthreads();
        for (int i = t; i < 8192; i += 256) {
            int c = i >> 9, q = i & 511;
            Qs[i] = g_Qt[b * (C8 * HWSZ) + c * HWSZ + ch * 512 + q];
        }
        __syncthreads();
        for (int i = 0; i < 16; i++) {
            int ql = lane + (i << 5);
            float s0 = 0.f, s1 = 0.f, s2 = 0.f, s3 = 0.f;
#pragma unroll
            for (int c = 0; c < 16; c++) {
                float qv = Qs[c * 512 + ql];
                s0 += key[c]      * qv;
                s1 += key[16 + c] * qv;
                s2 += key[32 + c] * qv;
                s3 += key[48 + c] * qv;
            }
            int qg = ch * 512 + ql;
            if (s0 > m[0]) { m[0] = s0; id[0] = qg; }
            if (s1 > m[1]) { m[1] = s1; id[1] = qg; }
            if (s2 > m[2]) { m[2] = s2; id[2] = qg; }
            if (s3 > m[3]) { m[3] = s3; id[3] = qg; }
        }
    }

    // warp reduce (max value, min index on tie = first occurrence)
#pragma unroll
    for (int off = 16; off; off >>= 1) {
#pragma unroll
        for (int r = 0; r < 4; r++) {
            float ov = __shfl_xor_sync(0xffffffffu, m[r], off);
            int   oi = __shfl_xor_sync(0xffffffffu, id[r], off);
            if (ov > m[r] || (ov == m[r] && oi < id[r])) { m[r] = ov; id[r] = oi; }
        }
    }
    if (lane == 0) {
#pragma unroll
        for (int r = 0; r < 4; r++) {
            int k = kbase + w * 4 + r;
            g_maxv[b * HWSZ + k] = m[r];
            g_idx [b * HWSZ + k] = id[r];
        }
    }
}

// ---------------- K3: gather selected values --------------------------------
__global__ void k3_gather() {
    int t = blockIdx.x * blockDim.x + threadIdx.x;
    if (t >= NB * NC * HWSZ) return;
    int p  = t & (HWSZ - 1);
    int bc = t >> 12;           // b*128 + c
    int b  = bc >> 7;
    g_sel[t] = g_V[(bc << 12) + g_idx[(b << 12) + p]];
}

// ---------------- K4: 3x3 conv (implicit GEMM, f32x2) + epilogue ------------
// grid (16 spatial tiles of 4 rows, 2 oc groups of 64, 4 batches), 256 threads.
// Thread: tx = lane (column within 32-col group), ty = warp -> 8 out channels.
// Register tile: 8 oc (4 f32x2 pairs) x 8 pixels.
__global__ __launch_bounds__(256, 1)
void k4_conv(const float* __restrict__ x,
             const float* __restrict__ bf,
             float* __restrict__ out) {
    __shared__ float patch[8 * 6 * 68];   // [ic][row 0..5][col 0..67], zero halo
    __shared__ float ws[8 * 9 * 64];      // [ic][tap][oc 64]
    int spt = blockIdx.x;          // 0..15
    int ocg = blockIdx.y;          // 0..1
    int b   = blockIdx.z;          // 0..3
    int t = threadIdx.x, tx = t & 31, ty = t >> 5;
    int h0 = spt * 4, p0 = spt * 256;

    unsigned long long acc[4][8];
#pragma unroll
    for (int k = 0; k < 4; k++)
#pragma unroll
        for (int j = 0; j < 8; j++) acc[k][j] = 0ull;

#pragma unroll 1
    for (int chunk = 0; chunk < 32; chunk++) {
        __syncthreads();
        // stage input patch (zero-padded halo)
        for (int i = t; i < 8 * 6 * 68; i += 256) {
            int ic  = i / 408;
            int rem = i - ic * 408;
            int r   = rem / 68;
            int c   = rem - r * 68;
            int gr = h0 - 1 + r, gc = c - 1;
            int icg = chunk * 8 + ic;
            float v = 0.f;
            if ((unsigned)gr < 64u && (unsigned)gc < 64u) {
                int off = gr * 64 + gc;
                v = (icg < 128) ? x[(b * 128 + icg) * HWSZ + off]
                                : g_sel[(b * 128 + (icg - 128)) * HWSZ + off];
            }
            patch[i] = v;
        }
        // stage weights [ic][tap][64 oc]
        for (int i = t; i < 8 * 9 * 64; i += 256) {
            int ic  = i / 576;
            int rem = i - ic * 576;
            int tap = rem >> 6;
            int oc  = rem & 63;
            ws[i] = g_Wt[(chunk * 8 + ic) * 1152 + tap * 128 + ocg * 64 + oc];
        }
        __syncthreads();

#pragma unroll 1
        for (int ic = 0; ic < 8; ic++) {
            const float* pr = &patch[ic * 408];
#pragma unroll
            for (int kh = 0; kh < 3; kh++) {
#pragma unroll
                for (int kw = 0; kw < 3; kw++) {
                    int tap = kh * 3 + kw;
                    const unsigned long long* wp =
                        (const unsigned long long*)&ws[ic * 576 + tap * 64 + ty * 8];
                    unsigned long long w0 = wp[0], w1 = wp[1], w2 = wp[2], w3 = wp[3];
                    int cb = tx + kw;
#pragma unroll
                    for (int j = 0; j < 8; j++) {
                        float xv = pr[((j >> 1) + kh) * 68 + cb + ((j & 1) << 5)];
                        unsigned long long xx = pack2(xv, xv);
                        ffma2(acc[0][j], w0, xx);
                        ffma2(acc[1][j], w1, xx);
                        ffma2(acc[2][j], w2, xx);
                        ffma2(acc[3][j], w3, xx);
                    }
                }
            }
        }
    }

    // epilogue: out = x + (conv + bf) * max_value
    int ocb = ocg * 64 + ty * 8;
#pragma unroll
    for (int j = 0; j < 8; j++) {
        int p  = p0 + tx + (j << 5);
        float mv = g_maxv[b * HWSZ + p];
#pragma unroll
        for (int k = 0; k < 4; k++) {
            float lo, hi;
            unpack2(acc[k][j], lo, hi);
            int oc = ocb + 2 * k;
            int o0 = (b * 128 + oc) * HWSZ + p;
            out[o0]        = x[o0]        + (lo + bf[oc])     * mv;
            out[o0 + HWSZ] = x[o0 + HWSZ] + (hi + bf[oc + 1]) * mv;
        }
    }
}

// ---------------- launch -----------------------------------------------------
extern "C" void kernel_launch(void* const* d_in, const int* in_sizes, int n_in,
                              void* d_out, int out_size) {
    const float* x  = (const float*)d_in[0];
    const float* xf = (const float*)d_in[1];
    const float* xb = (const float*)d_in[2];
    const float* Wq = (const float*)d_in[3];
    const float* bq = (const float*)d_in[4];
    const float* Wk = (const float*)d_in[5];
    const float* bk = (const float*)d_in[6];
    const float* Wv = (const float*)d_in[7];
    const float* bv = (const float*)d_in[8];
    const float* Wf = (const float*)d_in[9];
    const float* bf = (const float*)d_in[10];
    float* out = (float*)d_out;

    k0_transpose<<<256, 256>>>(Wq, Wk, Wv, Wf);
    k1_qkv<<<128, 128>>>(x, xf, xb, bq, bk, bv);
    k2_attn<<<512, 256>>>();
    k3_gather<<<(NB * NC * HWSZ + 255) / 256, 256>>>();
    k4_conv<<<dim3(16, 2, 4), 256>>>(x, bf, out);
}

// round 4
// speedup vs baseline: 1.1838x; 1.1838x over previous
#include <cuda_runtime.h>

// Problem constants
#define NB   4
#define NC   128
#define C8   16
#define HH   64
#define WW   64
#define HWSZ 4096   // 64*64

typedef unsigned long long ull;

// ---------------- scratch (static device globals; no runtime alloc) -------
__device__ float g_Qt [NB * C8 * HWSZ];     // [b][c8][p]
__device__ float g_Kt [NB * C8 * HWSZ];     // [b][c8][p]
__device__ float g_V  [NB * NC * HWSZ];     // [b][c][p]
__device__ float g_sel[NB * NC * HWSZ];     // [b][c][p]
__device__ float g_maxv[NB * HWSZ];
__device__ int   g_idx [NB * HWSZ];
__device__ float g_m8 [8 * NB * HWSZ];      // per-q-partition max
__device__ int   g_i8 [8 * NB * HWSZ];      // per-q-partition argmax
__device__ float g_part[2 * NB * NC * HWSZ];// split-K conv partials
__device__ float g_Wt [2 * NC * 9 * NC];    // [icg 256][tap 9][oc 128]
__device__ float g_WvT[NC * NC];            // [c][o]
__device__ float g_WqT[NC * C8];            // [c][o]
__device__ float g_WkT[NC * C8];            // [c][o]

// ---------------- f32x2 helpers (sm_103a packed fp32 FMA) -----------------
__device__ __forceinline__ ull pack2(float lo, float hi) {
    ull r;
    asm("mov.b64 %0, {%1, %2};" : "=l"(r)
        : "r"(__float_as_uint(lo)), "r"(__float_as_uint(hi)));
    return r;
}
__device__ __forceinline__ void unpack2(ull v, float& lo, float& hi) {
    unsigned ulo, uhi;
    asm("mov.b64 {%0, %1}, %2;" : "=r"(ulo), "=r"(uhi) : "l"(v));
    lo = __uint_as_float(ulo); hi = __uint_as_float(uhi);
}
__device__ __forceinline__ void ffma2(ull& d, ull a, ull b) {
    asm("fma.rn.f32x2 %0, %1, %2, %0;" : "+l"(d) : "l"(a), "l"(b));
}
// 128-bit shared load as two packed f32x2 operands (no repack movs)
__device__ __forceinline__ void lds128(ull& a, ull& b, const float* p) {
    unsigned addr = (unsigned)__cvta_generic_to_shared(p);
    asm volatile("ld.shared.v2.b64 {%0, %1}, [%2];"
                 : "=l"(a), "=l"(b) : "r"(addr));
}

// ---------------- K0: weight transposes -----------------------------------
__global__ void k0_transpose(const float* __restrict__ Wq,
                             const float* __restrict__ Wk,
                             const float* __restrict__ Wv,
                             const float* __restrict__ Wf) {
    int t = blockIdx.x * blockDim.x + threadIdx.x;
    int stride = gridDim.x * blockDim.x;
    for (int i = t; i < 256 * 9 * 128; i += stride) {
        int o = i & 127; int tap = (i >> 7) % 9; int ic = i / (128 * 9);
        g_Wt[i] = Wf[(o * 256 + ic) * 9 + tap];
    }
    for (int i = t; i < 128 * 128; i += stride) {
        int o = i & 127; int c = i >> 7;
        g_WvT[i] = Wv[o * 128 + c];
    }
    for (int i = t; i < 128 * 16; i += stride) {
        int o = i & 15; int c = i >> 4;
        g_WqT[i] = Wq[o * 128 + c];
        g_WkT[i] = Wk[o * 128 + c];
    }
}

// ---------------- K1: q/k/v 1x1 projections (f32x2) ------------------------
__global__ __launch_bounds__(128)
void k1_qkv(const float* __restrict__ x,
            const float* __restrict__ xf,
            const float* __restrict__ xb,
            const float* __restrict__ bq,
            const float* __restrict__ bk,
            const float* __restrict__ bv) {
    __shared__ float xs[64 * 128];
    __shared__ float wsf[64 * 32];
    int b  = blockIdx.x >> 5;
    int p0 = (blockIdx.x & 31) * 128;
    int t  = threadIdx.x;

    // ---- keys (Wk @ x + bk) ----
    {
        ull a[8];
#pragma unroll
        for (int o = 0; o < 8; o++) a[o] = pack2(bk[2 * o], bk[2 * o + 1]);
        for (int cc = 0; cc < 2; cc++) {
            __syncthreads();
            for (int c = 0; c < 64; c++)
                xs[c * 128 + t] = x[(b * 128 + cc * 64 + c) * HWSZ + p0 + t];
            for (int i = t; i < 64 * 16; i += 128)
                wsf[i] = g_WkT[cc * 64 * 16 + i];
            __syncthreads();
#pragma unroll 4
            for (int c = 0; c < 64; c++) {
                float xv = xs[c * 128 + t];
                ull xx = pack2(xv, xv);
                const float* wb = &wsf[c * 16];
                ull w0, w1, w2, w3, w4, w5, w6, w7;
                lds128(w0, w1, wb); lds128(w2, w3, wb + 4);
                lds128(w4, w5, wb + 8); lds128(w6, w7, wb + 12);
                ffma2(a[0], w0, xx); ffma2(a[1], w1, xx);
                ffma2(a[2], w2, xx); ffma2(a[3], w3, xx);
                ffma2(a[4], w4, xx); ffma2(a[5], w5, xx);
                ffma2(a[6], w6, xx); ffma2(a[7], w7, xx);
            }
        }
#pragma unroll
        for (int o = 0; o < 8; o++) {
            float lo, hi; unpack2(a[o], lo, hi);
            g_Kt[b * (C8 * HWSZ) + (2 * o) * HWSZ + p0 + t]     = lo;
            g_Kt[b * (C8 * HWSZ) + (2 * o + 1) * HWSZ + p0 + t] = hi;
        }
    }

    // ---- queries (Wq @ x_forward + bq) ----
    {
        ull a[8];
#pragma unroll
        for (int o = 0; o < 8; o++) a[o] = pack2(bq[2 * o], bq[2 * o + 1]);
        for (int cc = 0; cc < 2; cc++) {
            __syncthreads();
            for (int c = 0; c < 64; c++)
                xs[c * 128 + t] = xf[(b * 128 + cc * 64 + c) * HWSZ + p0 + t];
            for (int i = t; i < 64 * 16; i += 128)
                wsf[i] = g_WqT[cc * 64 * 16 + i];
            __syncthreads();
#pragma unroll 4
            for (int c = 0; c < 64; c++) {
                float xv = xs[c * 128 + t];
                ull xx = pack2(xv, xv);
                const float* wb = &wsf[c * 16];
                ull w0, w1, w2, w3, w4, w5, w6, w7;
                lds128(w0, w1, wb); lds128(w2, w3, wb + 4);
                lds128(w4, w5, wb + 8); lds128(w6, w7, wb + 12);
                ffma2(a[0], w0, xx); ffma2(a[1], w1, xx);
                ffma2(a[2], w2, xx); ffma2(a[3], w3, xx);
                ffma2(a[4], w4, xx); ffma2(a[5], w5, xx);
                ffma2(a[6], w6, xx); ffma2(a[7], w7, xx);
            }
        }
#pragma unroll
        for (int o = 0; o < 8; o++) {
            float lo, hi; unpack2(a[o], lo, hi);
            g_Qt[b * (C8 * HWSZ) + (2 * o) * HWSZ + p0 + t]     = lo;
            g_Qt[b * (C8 * HWSZ) + (2 * o + 1) * HWSZ + p0 + t] = hi;
        }
    }

    // ---- values (Wv @ x_backward + bv), 4 output groups of 32 ----
    for (int og = 0; og < 4; og++) {
        ull a[16];
#pragma unroll
        for (int o = 0; o < 16; o++)
            a[o] = pack2(bv[og * 32 + 2 * o], bv[og * 32 + 2 * o + 1]);
        for (int cc = 0; cc < 2; cc++) {
            __syncthreads();
            for (int c = 0; c < 64; c++)
                xs[c * 128 + t] = xb[(b * 128 + cc * 64 + c) * HWSZ + p0 + t];
            for (int i = t; i < 64 * 32; i += 128) {
                int c = i >> 5, o = i & 31;
                wsf[i] = g_WvT[(cc * 64 + c) * 128 + og * 32 + o];
            }
            __syncthreads();
#pragma unroll 2
            for (int c = 0; c < 64; c++) {
                float xv = xs[c * 128 + t];
                ull xx = pack2(xv, xv);
                const float* wb = &wsf[c * 32];
#pragma unroll
                for (int o4 = 0; o4 < 8; o4++) {
                    ull w0, w1;
                    lds128(w0, w1, wb + o4 * 4);
                    ffma2(a[o4 * 2 + 0], w0, xx);
                    ffma2(a[o4 * 2 + 1], w1, xx);
                }
            }
        }
#pragma unroll
        for (int o = 0; o < 16; o++) {
            float lo, hi; unpack2(a[o], lo, hi);
            g_V[(b * 128 + og * 32 + 2 * o) * HWSZ + p0 + t]     = lo;
            g_V[(b * 128 + og * 32 + 2 * o + 1) * HWSZ + p0 + t] = hi;
        }
    }
}

// ---------------- K2: attention row max/argmax (lane = key row) ------------
// grid 256 = 4 b x 8 key-blocks(512) x 8 q-partitions(512).
// Each lane owns 2 key rows held as duplicated f32x2 register vectors.
__global__ __launch_bounds__(256)
void k2_attn() {
    __shared__ float Qs[16 * 512];
    int bx = blockIdx.x;
    int qp = bx & 7;
    int kb = (bx >> 3) & 7;
    int b  = bx >> 6;
    int t = threadIdx.x, lane = t & 31, w = t >> 5;

    // stage this q-partition: Qs[c][512]
    for (int i = t; i < 8192; i += 256) {
        int c = i >> 9, q = i & 511;
        Qs[i] = g_Qt[b * (C8 * HWSZ) + c * HWSZ + qp * 512 + q];
    }

    // load 2 key rows per lane, duplicated-pair packed
    int k0 = kb * 512 + w * 64 + lane;
    ull kd0[16], kd1[16];
#pragma unroll
    for (int c = 0; c < 16; c++) {
        float v0 = g_Kt[b * (C8 * HWSZ) + c * HWSZ + k0];
        float v1 = g_Kt[b * (C8 * HWSZ) + c * HWSZ + k0 + 32];
        kd0[c] = pack2(v0, v0);
        kd1[c] = pack2(v1, v1);
    }
    __syncthreads();

    float m0 = -3.4e38f, m1 = -3.4e38f;
    int id0 = 0, id1 = 0;

#pragma unroll 1
    for (int i = 0; i < 128; i++) {
        const float* qbase = &Qs[4 * i];
        ull a0 = 0, a1 = 0, b0 = 0, b1 = 0;
#pragma unroll
        for (int c = 0; c < 16; c++) {
            ull q01, q23;
            lds128(q01, q23, qbase + c * 512);
            ffma2(a0, kd0[c], q01); ffma2(a1, kd0[c], q23);
            ffma2(b0, kd1[c], q01); ffma2(b1, kd1[c], q23);
        }
        int qg = qp * 512 + 4 * i;
        float s0, s1, s2, s3;
        unpack2(a0, s0, s1); unpack2(a1, s2, s3);
        if (s0 > m0) { m0 = s0; id0 = qg; }
        if (s1 > m0) { m0 = s1; id0 = qg + 1; }
        if (s2 > m0) { m0 = s2; id0 = qg + 2; }
        if (s3 > m0) { m0 = s3; id0 = qg + 3; }
        unpack2(b0, s0, s1); unpack2(b1, s2, s3);
        if (s0 > m1) { m1 = s0; id1 = qg; }
        if (s1 > m1) { m1 = s1; id1 = qg + 1; }
        if (s2 > m1) { m1 = s2; id1 = qg + 2; }
        if (s3 > m1) { m1 = s3; id1 = qg + 3; }
    }

    int base = (qp * NB + b) * HWSZ;
    g_m8[base + k0]      = m0;  g_i8[base + k0]      = id0;
    g_m8[base + k0 + 32] = m1;  g_i8[base + k0 + 32] = id1;
}

// merge the 8 q-partitions (ascending qp + strict > keeps first occurrence)
__global__ void k2_merge() {
    int t = blockIdx.x * blockDim.x + threadIdx.x;   // 16384 rows
    if (t >= NB * HWSZ) return;
    int b = t >> 12, k = t & (HWSZ - 1);
    float m = -3.4e38f; int id = 0;
#pragma unroll
    for (int qp = 0; qp < 8; qp++) {
        float v = g_m8[(qp * NB + b) * HWSZ + k];
        int   i = g_i8[(qp * NB + b) * HWSZ + k];
        if (v > m) { m = v; id = i; }
    }
    g_maxv[t] = m;
    g_idx [t] = id;
}

// ---------------- K3: gather selected values --------------------------------
__global__ void k3_gather() {
    int t = blockIdx.x * blockDim.x + threadIdx.x;
    if (t >= NB * NC * HWSZ) return;
    int p  = t & (HWSZ - 1);
    int bc = t >> 12;
    int b  = bc >> 7;
    g_sel[t] = g_V[(bc << 12) + g_idx[(b << 12) + p]];
}

// ---------------- K4: 3x3 conv (implicit GEMM, f32x2, split-K=2) ------------
// grid (16 spatial tiles, ocg(2) x half(2), 4 batches), 256 threads, 2 CTAs/SM.
__global__ __launch_bounds__(256, 2)
void k4_conv(const float* __restrict__ x) {
    __shared__ float patch[8 * 6 * 68];   // [ic][row 0..5][col 0..67], zero halo
    __shared__ float ws[8 * 9 * 64];      // [ic][tap][oc 64]
    int spt  = blockIdx.x;          // 0..15
    int ocg  = blockIdx.y & 1;
    int half = blockIdx.y >> 1;
    int b    = blockIdx.z;
    int t = threadIdx.x, tx = t & 31, ty = t >> 5;
    int h0 = spt * 4, p0 = spt * 256;

    ull acc[4][8];
#pragma unroll
    for (int k = 0; k < 4; k++)
#pragma unroll
        for (int j = 0; j < 8; j++) acc[k][j] = 0ull;

#pragma unroll 1
    for (int cc = 0; cc < 16; cc++) {
        int chunk = half * 16 + cc;
        __syncthreads();
        for (int i = t; i < 8 * 6 * 68; i += 256) {
            int ic  = i / 408;
            int rem = i - ic * 408;
            int r   = rem / 68;
            int c   = rem - r * 68;
            int gr = h0 - 1 + r, gc = c - 1;
            int icg = chunk * 8 + ic;
            float v = 0.f;
            if ((unsigned)gr < 64u && (unsigned)gc < 64u) {
                int off = gr * 64 + gc;
                v = (icg < 128) ? x[(b * 128 + icg) * HWSZ + off]
                                : g_sel[(b * 128 + (icg - 128)) * HWSZ + off];
            }
            patch[i] = v;
        }
        for (int i = t; i < 8 * 9 * 64; i += 256) {
            int ic  = i / 576;
            int rem = i - ic * 576;
            int tap = rem >> 6;
            int oc  = rem & 63;
            ws[i] = g_Wt[(chunk * 8 + ic) * 1152 + tap * 128 + ocg * 64 + oc];
        }
        __syncthreads();

#pragma unroll 1
        for (int ic = 0; ic < 8; ic++) {
            const float* pr = &patch[ic * 408];
#pragma unroll
            for (int kh = 0; kh < 3; kh++) {
#pragma unroll
                for (int kw = 0; kw < 3; kw++) {
                    int tap = kh * 3 + kw;
                    const float* wb = &ws[ic * 576 + tap * 64 + ty * 8];
                    ull w0, w1, w2, w3;
                    lds128(w0, w1, wb);
                    lds128(w2, w3, wb + 4);
                    int cb = tx + kw;
#pragma unroll
                    for (int j = 0; j < 8; j++) {
                        float xv = pr[((j >> 1) + kh) * 68 + cb + ((j & 1) << 5)];
                        ull xx = pack2(xv, xv);
                        ffma2(acc[0][j], w0, xx);
                        ffma2(acc[1][j], w1, xx);
                        ffma2(acc[2][j], w2, xx);
                        ffma2(acc[3][j], w3, xx);
                    }
                }
            }
        }
    }

    // write split-K partials (no bias/scale yet)
    int ocb = ocg * 64 + ty * 8;
    float* dst = &g_part[((half * NB + b) * NC) * HWSZ];
#pragma unroll
    for (int j = 0; j < 8; j++) {
        int p = p0 + tx + (j << 5);
#pragma unroll
        for (int k = 0; k < 4; k++) {
            float lo, hi;
            unpack2(acc[k][j], lo, hi);
            int oc = ocb + 2 * k;
            dst[oc * HWSZ + p]       = lo;
            dst[(oc + 1) * HWSZ + p] = hi;
        }
    }
}

// ---------------- K5: epilogue out = x + (p0+p1+bias)*max ------------------
__global__ void k5_epilogue(const float* __restrict__ x,
                            const float* __restrict__ bf,
                            float* __restrict__ out) {
    int i = blockIdx.x * blockDim.x + threadIdx.x;
    if (i >= NB * NC * HWSZ) return;
    int p  = i & (HWSZ - 1);
    int oc = (i >> 12) & 127;
    int b  = i >> 19;
    float s = g_part[i] + g_part[i + NB * NC * HWSZ] + bf[oc];
    out[i] = x[i] + s * g_maxv[(b << 12) | p];
}

// ---------------- launch -----------------------------------------------------
extern "C" void kernel_launch(void* const* d_in, const int* in_sizes, int n_in,
                              void* d_out, int out_size) {
    const float* x  = (const float*)d_in[0];
    const float* xf = (const float*)d_in[1];
    const float* xb = (const float*)d_in[2];
    const float* Wq = (const float*)d_in[3];
    const float* bq = (const float*)d_in[4];
    const float* Wk = (const float*)d_in[5];
    const float* bk = (const float*)d_in[6];
    const float* Wv = (const float*)d_in[7];
    const float* bv = (const float*)d_in[8];
    const float* Wf = (const float*)d_in[9];
    const float* bf = (const float*)d_in[10];
    float* out = (float*)d_out;

    k0_transpose<<<256, 256>>>(Wq, Wk, Wv, Wf);
    k1_qkv<<<128, 128>>>(x, xf, xb, bq, bk, bv);
    k2_attn<<<256, 256>>>();
    k2_merge<<<64, 256>>>();
    k3_gather<<<(NB * NC * HWSZ + 255) / 256, 256>>>();
    k4_conv<<<dim3(16, 4, 4), 256>>>(x);
    k5_epilogue<<<(NB * NC * HWSZ + 255) / 256, 256>>>(x, bf, out);
}